// round 14
// baseline (speedup 1.0000x reference)
#include <cuda_runtime.h>
#include <cuda_bf16.h>
#include <cuda_fp16.h>
#include <cstdint>

#define N_TOK 2048
#define DIM   32
#define RFEAT 64
#define HDIM  128
#define NSUP  (N_TOK / 128)     // 16 supertiles of 128 j

// ---------- scratch (device globals; no allocation allowed) ----------
__device__ __align__(16) float    g_V[N_TOK * DIM];
__device__ __align__(16) float    g_phiQ[N_TOK * RFEAT];
__device__ __align__(16) unsigned g_phiQh2[N_TOK * (RFEAT / 2)]; // row-major bf16x2 r-pairs
__device__ __align__(16) unsigned g_phiKh2[N_TOK * (RFEAT / 2)];
__device__ __align__(16) uint2    g_KT4[(DIM / 4) * N_TOK];      // [k4][j]: 4 fp16 k-values per col
__device__ __align__(16) unsigned g_Qh2[N_TOK * (DIM / 2)];      // [i][k2] fp16x2 k-pairs
__device__ __align__(16) unsigned g_VT2[DIM * (N_TOK / 2)];      // [c][j2] bf16x2 j-pairs
__device__ __align__(16) float    g_M[RFEAT * DIM];              // phi_K^T @ V (atomic accum)

__device__ __forceinline__ float fast_ex2(float x) {
    float y;
    asm("ex2.approx.ftz.f32 %0, %1;" : "=f"(y) : "f"(x));
    return y;
}
__device__ __forceinline__ __half2 h2ex2(__half2 x) {
    __half2 y;
    asm("ex2.approx.f16x2 %0, %1;" : "=r"(*(unsigned*)&y) : "r"(*(unsigned*)&x));
    return y;
}
__device__ __forceinline__ __half2 u2h(unsigned u) { return *reinterpret_cast<__half2*>(&u); }

__device__ __forceinline__ float warp_sum(float v) {
    v += __shfl_xor_sync(0xffffffffu, v, 16);
    v += __shfl_xor_sync(0xffffffffu, v, 8);
    v += __shfl_xor_sync(0xffffffffu, v, 4);
    v += __shfl_xor_sync(0xffffffffu, v, 2);
    v += __shfl_xor_sync(0xffffffffu, v, 1);
    return v;
}
__device__ __forceinline__ unsigned packbf(float a, float b) {
    __nv_bfloat162 h = __floats2bfloat162_rn(a, b);
    return *reinterpret_cast<unsigned*>(&h);
}
__device__ __forceinline__ unsigned packh(float a, float b) {
    __half2 h = __floats2half2_rn(a, b);
    return *reinterpret_cast<unsigned*>(&h);
}
#define BFLO(u) __uint_as_float((u) << 16)
#define BFHI(u) __uint_as_float((u) & 0xffff0000u)

#define CP_ASYNC16(dst_s, src_g) \
    asm volatile("cp.async.cg.shared.global [%0], [%1], 16;" :: "r"(dst_s), "l"(src_g))
#define CP_COMMIT() asm volatile("cp.async.commit_group;")
#define CP_WAIT0()  asm volatile("cp.async.wait_group 0;" ::: "memory")

#define L2E    1.4426950408889634f
#define KSCALE ((float)(1.4426950408889634 / 5.6568542494923806)) // log2e/sqrt(32)

// ---------------------------------------------------------------------
// K1: warp-per-row QKV + norms + random features + partial phiK^T V
// (atomicAdd into g_M). 16 rows/block, 512 threads, grid 128.
// ---------------------------------------------------------------------
__global__ void __launch_bounds__(512) k1_proj(const float* __restrict__ Z,
                        const float* __restrict__ Wq, const float* __restrict__ bq,
                        const float* __restrict__ Wk, const float* __restrict__ bk,
                        const float* __restrict__ Wv, const float* __restrict__ bv,
                        const float* __restrict__ omega)
{
    __shared__ float sW[3][DIM * DIM];
    __shared__ float sB[3][DIM];
    __shared__ float sOm[DIM * RFEAT];
    __shared__ float sRow[16][DIM];
    __shared__ float sAn[16][DIM];
    __shared__ float sK[16][33];
    __shared__ float sVv[16][33];
    __shared__ float sQf[16][33];
    __shared__ float sPK[16][RFEAT];

    int tid = threadIdx.x, lane = tid & 31, w = tid >> 5;
    for (int idx = tid; idx < DIM * DIM; idx += 512) {
        sW[0][idx] = Wq[idx]; sW[1][idx] = Wk[idx]; sW[2][idx] = Wv[idx];
    }
    for (int idx = tid; idx < DIM * RFEAT; idx += 512) sOm[idx] = omega[idx];
    if (tid < DIM) { sB[0][tid] = bq[tid]; sB[1][tid] = bk[tid]; sB[2][tid] = bv[tid]; }

    int i0 = blockIdx.x * 16;
    int i = i0 + w;
    float zk = Z[i * DIM + lane];
    __syncthreads();

    sRow[w][lane] = zk;
    __syncwarp();

    float a[3];
    #pragma unroll
    for (int p = 0; p < 3; p++) {
        float s0 = sB[p][lane], s1 = 0.f;
        #pragma unroll
        for (int k = 0; k < DIM; k += 2) {
            s0 = fmaf(sRow[w][k],     sW[p][k * DIM + lane],       s0);
            s1 = fmaf(sRow[w][k + 1], sW[p][(k + 1) * DIM + lane], s1);
        }
        a[p] = s0 + s1;
    }
    g_V[i * DIM + lane] = a[2];
    sQf[w][lane] = a[0];
    sK[w][lane]  = a[1] * KSCALE;
    sVv[w][lane] = a[2];

    #pragma unroll
    for (int p = 0; p < 2; p++) {
        float v = a[p];
        float ss = warp_sum(v * v);
        float an = v * (1.f / fmaxf(sqrtf(ss), 1e-6f));
        sAn[w][lane] = an;
        __syncwarp();
        float d0 = 0.f, d1 = 0.f, d2 = 0.f, d3 = 0.f;
        #pragma unroll
        for (int k = 0; k < DIM; k += 2) {
            float ab0 = sAn[w][k], ab1 = sAn[w][k + 1];
            float2 om0 = *(const float2*)&sOm[k * RFEAT + 2 * lane];
            float2 om1 = *(const float2*)&sOm[(k + 1) * RFEAT + 2 * lane];
            d0 = fmaf(ab0, om0.x, d0); d1 = fmaf(ab0, om0.y, d1);
            d2 = fmaf(ab1, om1.x, d2); d3 = fmaf(ab1, om1.y, d3);
        }
        float e0 = fast_ex2((d0 + d2) * L2E) * 0.125f;  // exp(d)/sqrt(r), r=64
        float e1 = fast_ex2((d1 + d3) * L2E) * 0.125f;
        float2 ph; ph.x = e0; ph.y = e1;
        if (p == 0) {
            *(float2*)&g_phiQ[i * RFEAT + 2 * lane] = ph;
            g_phiQh2[i * (RFEAT / 2) + lane] = packbf(e0, e1);
        } else {
            sPK[w][2 * lane] = e0; sPK[w][2 * lane + 1] = e1;
            g_phiKh2[i * (RFEAT / 2) + lane] = packbf(e0, e1);
        }
        __syncwarp();
    }

    __syncthreads();
    if (tid < 256) {
        // V^T bf16x2 j-pairs, q fp16x2 k-pairs
        int k = tid >> 3, p = tid & 7;
        g_VT2[k * (N_TOK / 2) + (i0 >> 1) + p] = packbf(sVv[2 * p][k], sVv[2 * p + 1][k]);
        int k2 = tid >> 4, r = tid & 15;
        g_Qh2[(i0 + r) * (DIM / 2) + k2] = packh(sQf[r][2 * k2], sQf[r][2 * k2 + 1]);
    }
    if (tid < 128) {
        // K^T k-quad entries [k4][j]
        int k4 = tid >> 4, r = tid & 15;
        g_KT4[k4 * N_TOK + i0 + r] = make_uint2(
            packh(sK[r][4 * k4 + 0], sK[r][4 * k4 + 1]),
            packh(sK[r][4 * k4 + 2], sK[r][4 * k4 + 3]));
    }

    // partial M = phiK_blk^T @ V_blk -> atomicAdd (4 outputs/thread)
    {
        int r  = tid >> 3;
        int c0 = (tid & 7) * 4;
        float m0 = 0.f, m1 = 0.f, m2 = 0.f, m3 = 0.f;
        #pragma unroll
        for (int ii = 0; ii < 16; ii++) {
            float pk = sPK[ii][r];
            m0 = fmaf(pk, sVv[ii][c0 + 0], m0);
            m1 = fmaf(pk, sVv[ii][c0 + 1], m1);
            m2 = fmaf(pk, sVv[ii][c0 + 2], m2);
            m3 = fmaf(pk, sVv[ii][c0 + 3], m3);
        }
        atomicAdd(&g_M[r * DIM + c0 + 0], m0);
        atomicAdd(&g_M[r * DIM + c0 + 1], m1);
        atomicAdd(&g_M[r * DIM + c0 + 2], m2);
        atomicAdd(&g_M[r * DIM + c0 + 3], m3);
    }
}

// ---------------------------------------------------------------------
// K3: attention, software-pipelined: exp(t) & AV(t-1) in the same
// iteration (MUFU overlaps FMA/LDS). Fused phi-mma (parity groups,
// lookahead 2, triple sP), fused epilogue. 1024 thr, 16 rows, grid 128.
// Dynamic smem (byte offsets):
//   0      sKT  [2][8][128]uint2 16384  (k-quad rows, 1024B each)
//   16384  sVT2 [3][32][68]u32   26112 -> 42496
//   42496  sP   [3][16][128]f32  24576 -> 67072
//   67072  sS   [2][16][128]f32  16384 -> 83456
//   83456  sPQ  [16][64]f32       4096 -> 87552
//   87552  sWo  [32][32]f32       4096 -> 91648
//   91648  sAcc [32][32]f32       4096 -> 95744
//   95744  sVec [6][32]f32         768 -> 96512
//   96512  sb1  [128]f32           512 -> 97024
//   97024  sZ1  [16][32]f32       2048 -> 99072
// Epilogue overlay in [0, 67072): sM@0, sW1@8192, sW2@24576, sH@40960.
// ---------------------------------------------------------------------
#define K3_SMEM_BYTES 99072

__device__ __forceinline__ void k3_stage(int t, int tid, unsigned base)
{
    if (tid < 512) {
        int k4 = tid >> 6, c = tid & 63;
        CP_ASYNC16(base + (unsigned)((t & 1) * 8192 + k4 * 1024 + c * 16),
                   g_KT4 + k4 * N_TOK + t * 128 + c * 2);
    } else {
        int idx = tid - 512;
        int row = idx >> 4, c = idx & 15;
        CP_ASYNC16(base + (unsigned)(16384 + (t % 3) * 8704 + row * 272 + c * 16),
                   g_VT2 + row * (N_TOK / 2) + t * 64 + c * 4);
    }
}

__global__ void __launch_bounds__(1024, 1) k3_attn(
    const int* __restrict__ mask,
    const float* __restrict__ Wo, const float* __restrict__ bo,
    const float* __restrict__ Z,
    const float* __restrict__ W1, const float* __restrict__ b1,
    const float* __restrict__ W2, const float* __restrict__ b2,
    const float* __restrict__ g1, const float* __restrict__ be1,
    const float* __restrict__ g2, const float* __restrict__ be2,
    float* __restrict__ out)
{
    extern __shared__ char sm_raw[];
    unsigned smem_base = (unsigned)__cvta_generic_to_shared(sm_raw);
    float* sP   = (float*)(sm_raw + 42496);
    float* sS   = (float*)(sm_raw + 67072);
    float* sPQ  = (float*)(sm_raw + 83456);
    float* sWo  = (float*)(sm_raw + 87552);
    float* sAcc = (float*)(sm_raw + 91648);
    float* sVec = (float*)(sm_raw + 95744);
    float* sb1  = (float*)(sm_raw + 96512);
    float* sZ1  = (float*)(sm_raw + 97024);
    // epilogue overlay
    float* sM   = (float*)(sm_raw);
    float* sW1  = (float*)(sm_raw + 8192);
    float* sW2  = (float*)(sm_raw + 24576);
    float* sH   = (float*)(sm_raw + 40960);

    int tid = threadIdx.x, lane = tid & 31, w = tid >> 5;
    int r16 = w >> 1, h = w & 1;
    int g   = lane >> 2, tig = lane & 3;       // mma fragment coords
    int wt  = w & 15;                          // mma n8-tile index
    int i0 = blockIdx.x * 16;
    int i  = i0 + r16;

    // stage persistent data
    sPQ[tid] = g_phiQ[i0 * RFEAT + tid];
    for (int idx = tid; idx < DIM * DIM; idx += 1024) sWo[idx] = Wo[idx];
    if (tid < HDIM) sb1[tid] = b1[tid];
    if (tid < DIM) {
        sVec[tid] = bo[tid];        sVec[32 + tid] = b2[tid];
        sVec[64 + tid] = g1[tid];   sVec[96 + tid] = be1[tid];
        sVec[128 + tid] = g2[tid];  sVec[160 + tid] = be2[tid];
    }

    // q fp16x2 k-pairs: loop-invariant registers
    __half2 qreg[16];
    {
        const uint4* qp = (const uint4*)(g_Qh2 + i * (DIM / 2));
        #pragma unroll
        for (int u = 0; u < 4; u++) {
            uint4 t4 = qp[u];
            qreg[u * 4 + 0] = u2h(t4.x); qreg[u * 4 + 1] = u2h(t4.y);
            qreg[u * 4 + 2] = u2h(t4.z); qreg[u * 4 + 3] = u2h(t4.w);
        }
    }

    // A-fragments (phiQ rows i0..i0+15): loop-invariant
    unsigned afrag[16];
    #pragma unroll
    for (int ks = 0; ks < 4; ks++) {
        int kp = ks * 8 + tig;
        afrag[ks * 4 + 0] = g_phiQh2[(i0 + g)     * 32 + kp];
        afrag[ks * 4 + 1] = g_phiQh2[(i0 + g + 8) * 32 + kp];
        afrag[ks * 4 + 2] = g_phiQh2[(i0 + g)     * 32 + kp + 4];
        afrag[ks * 4 + 3] = g_phiQh2[(i0 + g + 8) * 32 + kp + 4];
    }

    const int2* mrow2 = (const int2*)(mask + (size_t)i * N_TOK);
    float acc = 0.f;
    int jb = h * 64 + 2 * lane;

    k3_stage(0, tid, smem_base);
    CP_COMMIT();

    // prologue mma: group A -> P(0), group B -> P(1)
    {
        int tn = (w < 16) ? 0 : 1;
        int jn0 = tn * 128 + wt * 8;
        float d0 = 0.f, d1 = 0.f, d2 = 0.f, d3 = 0.f;
        #pragma unroll
        for (int ks = 0; ks < 4; ks++) {
            int kp = ks * 8 + tig;
            unsigned b0 = g_phiKh2[(jn0 + g) * 32 + kp];
            unsigned b1 = g_phiKh2[(jn0 + g) * 32 + kp + 4];
            asm volatile(
                "mma.sync.aligned.m16n8k16.row.col.f32.bf16.bf16.f32 "
                "{%0,%1,%2,%3}, {%4,%5,%6,%7}, {%8,%9}, {%0,%1,%2,%3};"
                : "+f"(d0), "+f"(d1), "+f"(d2), "+f"(d3)
                : "r"(afrag[ks*4+0]), "r"(afrag[ks*4+1]),
                  "r"(afrag[ks*4+2]), "r"(afrag[ks*4+3]), "r"(b0), "r"(b1));
        }
        float* sPb = sP + tn * 2048;
        int jc = wt * 8 + 2 * tig;
        *(float2*)&sPb[g * 128 + jc]       = make_float2(d0, d1);
        *(float2*)&sPb[(g + 8) * 128 + jc] = make_float2(d2, d3);
    }

    int pr = 0;
    for (int t = 0; t < NSUP; t++) {
        CP_WAIT0();
        __syncthreads();
        if (t + 1 < NSUP) { k3_stage(t + 1, tid, smem_base); CP_COMMIT(); }

        // pipelined mma: P(t+2) by parity group
        int tn = t + 2;
        if (tn < NSUP && ((tn & 1) ? (w >= 16) : (w < 16))) {
            int jn0 = tn * 128 + wt * 8;
            float d0 = 0.f, d1 = 0.f, d2 = 0.f, d3 = 0.f;
            #pragma unroll
            for (int ks = 0; ks < 4; ks++) {
                int kp = ks * 8 + tig;
                unsigned b0 = g_phiKh2[(jn0 + g) * 32 + kp];
                unsigned b1 = g_phiKh2[(jn0 + g) * 32 + kp + 4];
                asm volatile(
                    "mma.sync.aligned.m16n8k16.row.col.f32.bf16.bf16.f32 "
                    "{%0,%1,%2,%3}, {%4,%5,%6,%7}, {%8,%9}, {%0,%1,%2,%3};"
                    : "+f"(d0), "+f"(d1), "+f"(d2), "+f"(d3)
                    : "r"(afrag[ks*4+0]), "r"(afrag[ks*4+1]),
                      "r"(afrag[ks*4+2]), "r"(afrag[ks*4+3]), "r"(b0), "r"(b1));
            }
            int pw = pr + 2; if (pw >= 3) pw -= 3;
            float* sPb = sP + pw * 2048;
            int jc = wt * 8 + 2 * tig;
            *(float2*)&sPb[g * 128 + jc]       = make_float2(d0, d1);
            *(float2*)&sPb[(g + 8) * 128 + jc] = make_float2(d2, d3);
        }

        // ---- exp(t): k-quad LDS.128 loads, dual-ex2 ----
        {
            const uint4* KT4 = (const uint4*)(sm_raw + (t & 1) * 8192);
            int vidx = h * 32 + lane;
            int2 mv = mrow2[t * 64 + h * 32 + lane];
            __half2 aA0 = __floats2half2_rn(0.f, 0.f);
            __half2 aA1 = aA0, aB0 = aA0, aB1 = aA0;
            #pragma unroll
            for (int k4 = 0; k4 < 8; k4++) {
                uint4 kk = KT4[k4 * 64 + vidx];
                aA0 = __hadd2(aA0, h2ex2(__hmul2(qreg[2 * k4],     u2h(kk.x))));
                aA1 = __hadd2(aA1, h2ex2(__hmul2(qreg[2 * k4 + 1], u2h(kk.y))));
                aB0 = __hadd2(aB0, h2ex2(__hmul2(qreg[2 * k4],     u2h(kk.z))));
                aB1 = __hadd2(aB1, h2ex2(__hmul2(qreg[2 * k4 + 1], u2h(kk.w))));
            }
            float eA = (__low2float(aA0) + __high2float(aA0)) + (__low2float(aA1) + __high2float(aA1));
            float eB = (__low2float(aB0) + __high2float(aB0)) + (__low2float(aB1) + __high2float(aB1));

            float2 Pw = *(const float2*)&sP[pr * 2048 + r16 * 128 + jb];
            float2 sv;
            sv.x = (mv.x == 0) ? (eA - Pw.x) : 0.f;
            sv.y = (mv.y == 0) ? (eB - Pw.y) : 0.f;
            *(float2*)&sS[(t & 1) * 2048 + r16 * 128 + jb] = sv;
        }

        // ---- AV(t-1): overlaps exp(t)'s MUFU stream ----
        if (t > 0) {
            const unsigned* VT = (const unsigned*)(sm_raw + 16384 + ((t - 1) % 3) * 8704)
                                 + lane * 68 + h * 32;
            const float4* SS = (const float4*)&sS[((t - 1) & 1) * 2048 + r16 * 128 + h * 64];
            #pragma unroll
            for (int j8 = 0; j8 < 8; j8++) {
                uint4 v = *(const uint4*)(VT + j8 * 4);
                float4 s0 = SS[2 * j8], s1 = SS[2 * j8 + 1];
                acc = fmaf(s0.x, BFLO(v.x), acc); acc = fmaf(s0.y, BFHI(v.x), acc);
                acc = fmaf(s0.z, BFLO(v.y), acc); acc = fmaf(s0.w, BFHI(v.y), acc);
                acc = fmaf(s1.x, BFLO(v.z), acc); acc = fmaf(s1.y, BFHI(v.z), acc);
                acc = fmaf(s1.z, BFLO(v.w), acc); acc = fmaf(s1.w, BFHI(v.w), acc);
            }
        }
        pr = pr + 1; if (pr >= 3) pr = 0;
    }

    // final AV for tile 15 (sS[1], VT buffer 15%3 = 0)
    __syncwarp();
    {
        const unsigned* VT = (const unsigned*)(sm_raw + 16384 + (15 % 3) * 8704)
                             + lane * 68 + h * 32;
        const float4* SS = (const float4*)&sS[(15 & 1) * 2048 + r16 * 128 + h * 64];
        #pragma unroll
        for (int j8 = 0; j8 < 8; j8++) {
            uint4 v = *(const uint4*)(VT + j8 * 4);
            float4 s0 = SS[2 * j8], s1 = SS[2 * j8 + 1];
            acc = fmaf(s0.x, BFLO(v.x), acc); acc = fmaf(s0.y, BFHI(v.x), acc);
            acc = fmaf(s0.z, BFLO(v.y), acc); acc = fmaf(s0.w, BFHI(v.y), acc);
            acc = fmaf(s1.x, BFLO(v.z), acc); acc = fmaf(s1.y, BFHI(v.z), acc);
            acc = fmaf(s1.z, BFLO(v.w), acc); acc = fmaf(s1.w, BFHI(v.w), acc);
        }
    }

    // ---- epilogue ----
    __syncthreads();
    for (int idx = tid; idx < RFEAT * DIM; idx += 1024) sM[idx] = g_M[idx];
    for (int idx = tid; idx < DIM * HDIM; idx += 1024) { sW1[idx] = W1[idx]; sW2[idx] = W2[idx]; }
    sAcc[w * 32 + lane] = acc;
    __syncthreads();

    if (h == 0) {
        float lr = 0.f;
        #pragma unroll
        for (int r = 0; r < RFEAT; r++) lr = fmaf(sPQ[r16 * RFEAT + r], sM[r * DIM + lane], lr);

        float attn = sAcc[w * 32 + lane] + sAcc[(w + 1) * 32 + lane] + lr;
        float denom = fmaxf(warp_sum(attn), 1e-6f);
        float a = attn / denom;

        sAcc[w * 32 + lane] = a;
        __syncwarp();
        float o = sVec[lane];   // bo
        #pragma unroll
        for (int c = 0; c < DIM; c++) o = fmaf(sAcc[w * 32 + c], sWo[c * DIM + lane], o);

        // LN1
        float x = Z[i * DIM + lane] + o;
        float mu = warp_sum(x) * (1.f / 32.f);
        float dd = x - mu;
        float var = warp_sum(dd * dd) * (1.f / 32.f);
        float z1 = dd * rsqrtf(var + 1e-5f) * sVec[64 + lane] + sVec[96 + lane];
        sZ1[r16 * DIM + lane] = z1;
        __syncwarp();

        // FFN up + relu
        float hh[4];
        #pragma unroll
        for (int u = 0; u < 4; u++) hh[u] = sb1[lane + u * 32];
        #pragma unroll
        for (int k = 0; k < DIM; k++) {
            float zk = sZ1[r16 * DIM + k];
            #pragma unroll
            for (int u = 0; u < 4; u++) hh[u] = fmaf(zk, sW1[k * HDIM + lane + u * 32], hh[u]);
        }
        #pragma unroll
        for (int u = 0; u < 4; u++) sH[r16 * HDIM + lane + u * 32] = fmaxf(hh[u], 0.f);
        __syncwarp();

        // FFN down
        float o0 = sVec[32 + lane], o1 = 0.f, o2 = 0.f, o3 = 0.f;
        #pragma unroll
        for (int j = 0; j < HDIM; j += 4) {
            o0 = fmaf(sH[r16 * HDIM + j + 0], sW2[(j + 0) * DIM + lane], o0);
            o1 = fmaf(sH[r16 * HDIM + j + 1], sW2[(j + 1) * DIM + lane], o1);
            o2 = fmaf(sH[r16 * HDIM + j + 2], sW2[(j + 2) * DIM + lane], o2);
            o3 = fmaf(sH[r16 * HDIM + j + 3], sW2[(j + 3) * DIM + lane], o3);
        }
        float y = z1 + ((o0 + o1) + (o2 + o3));

        // LN2
        float mu2 = warp_sum(y) * (1.f / 32.f);
        float dd2 = y - mu2;
        float var2 = warp_sum(dd2 * dd2) * (1.f / 32.f);
        out[i * DIM + lane] = dd2 * rsqrtf(var2 + 1e-5f) * sVec[128 + lane] + sVec[160 + lane];
    }
}

// ---------------------------------------------------------------------
extern "C" void kernel_launch(void* const* d_in, const int* in_sizes, int n_in,
                              void* d_out, int out_size)
{
    const float* Z    = (const float*)d_in[0];
    const int*   mask = (const int*)  d_in[1];
    const float* Wq = (const float*)d_in[2],  *bq = (const float*)d_in[3];
    const float* Wk = (const float*)d_in[4],  *bk = (const float*)d_in[5];
    const float* Wv = (const float*)d_in[6],  *bv = (const float*)d_in[7];
    const float* Wo = (const float*)d_in[8],  *bo = (const float*)d_in[9];
    const float* W1 = (const float*)d_in[10], *b1 = (const float*)d_in[11];
    const float* W2 = (const float*)d_in[12], *b2 = (const float*)d_in[13];
    const float* g1 = (const float*)d_in[14], *be1 = (const float*)d_in[15];
    const float* g2 = (const float*)d_in[16], *be2 = (const float*)d_in[17];
    const float* omega = (const float*)d_in[18];

    cudaFuncSetAttribute(k3_attn, cudaFuncAttributeMaxDynamicSharedMemorySize, K3_SMEM_BYTES);

    void* mptr = nullptr;
    cudaGetSymbolAddress(&mptr, g_M);
    cudaMemsetAsync(mptr, 0, RFEAT * DIM * sizeof(float));

    k1_proj<<<N_TOK / 16, 512>>>(Z, Wq, bq, Wk, bk, Wv, bv, omega);
    k3_attn<<<N_TOK / 16, 1024, K3_SMEM_BYTES>>>(mask, Wo, bo, Z,
                                                 W1, b1, W2, b2,
                                                 g1, be1, g2, be2, (float*)d_out);
}

// round 15
// speedup vs baseline: 1.0435x; 1.0435x over previous
#include <cuda_runtime.h>
#include <cuda_bf16.h>
#include <cuda_fp16.h>
#include <cstdint>

#define N_TOK 2048
#define DIM   32
#define RFEAT 64
#define HDIM  128
#define NSUP  (N_TOK / 128)     // 16 supertiles of 128 j

// ---------- scratch (device globals; no allocation allowed) ----------
__device__ __align__(16) float    g_V[N_TOK * DIM];
__device__ __align__(16) float    g_phiQ[N_TOK * RFEAT];
__device__ __align__(16) unsigned g_phiQh2[N_TOK * (RFEAT / 2)]; // row-major bf16x2 r-pairs
__device__ __align__(16) unsigned g_phiKh2[N_TOK * (RFEAT / 2)];
__device__ __align__(16) uint2    g_KT4[(DIM / 4) * N_TOK];      // [k4][j]: 4 fp16 k-values per col
__device__ __align__(16) unsigned g_Qh2[N_TOK * (DIM / 2)];      // [i][k2] fp16x2 k-pairs
__device__ __align__(16) unsigned g_VT2[DIM * (N_TOK / 2)];      // [c][j2] bf16x2 j-pairs
__device__ __align__(16) float    g_M[RFEAT * DIM];              // phi_K^T @ V (atomic accum)

__device__ __forceinline__ float fast_ex2(float x) {
    float y;
    asm("ex2.approx.ftz.f32 %0, %1;" : "=f"(y) : "f"(x));
    return y;
}
__device__ __forceinline__ __half2 h2ex2(__half2 x) {
    __half2 y;
    asm("ex2.approx.f16x2 %0, %1;" : "=r"(*(unsigned*)&y) : "r"(*(unsigned*)&x));
    return y;
}
__device__ __forceinline__ __half2 u2h(unsigned u) { return *reinterpret_cast<__half2*>(&u); }

__device__ __forceinline__ float warp_sum(float v) {
    v += __shfl_xor_sync(0xffffffffu, v, 16);
    v += __shfl_xor_sync(0xffffffffu, v, 8);
    v += __shfl_xor_sync(0xffffffffu, v, 4);
    v += __shfl_xor_sync(0xffffffffu, v, 2);
    v += __shfl_xor_sync(0xffffffffu, v, 1);
    return v;
}
__device__ __forceinline__ unsigned packbf(float a, float b) {
    __nv_bfloat162 h = __floats2bfloat162_rn(a, b);
    return *reinterpret_cast<unsigned*>(&h);
}
__device__ __forceinline__ unsigned packh(float a, float b) {
    __half2 h = __floats2half2_rn(a, b);
    return *reinterpret_cast<unsigned*>(&h);
}
#define BFLO(u) __uint_as_float((u) << 16)
#define BFHI(u) __uint_as_float((u) & 0xffff0000u)

#define CP_ASYNC16(dst_s, src_g) \
    asm volatile("cp.async.cg.shared.global [%0], [%1], 16;" :: "r"(dst_s), "l"(src_g))
#define CP_COMMIT() asm volatile("cp.async.commit_group;")
#define CP_WAIT0()  asm volatile("cp.async.wait_group 0;" ::: "memory")

#define L2E    1.4426950408889634f
#define KSCALE ((float)(1.4426950408889634 / 5.6568542494923806)) // log2e/sqrt(32)

// ---------------------------------------------------------------------
// K1: warp-per-row QKV + norms + random features + partial phiK^T V
// (atomicAdd into g_M). 16 rows/block, 512 threads, grid 128.
// ---------------------------------------------------------------------
__global__ void __launch_bounds__(512) k1_proj(const float* __restrict__ Z,
                        const float* __restrict__ Wq, const float* __restrict__ bq,
                        const float* __restrict__ Wk, const float* __restrict__ bk,
                        const float* __restrict__ Wv, const float* __restrict__ bv,
                        const float* __restrict__ omega)
{
    __shared__ float sW[3][DIM * DIM];
    __shared__ float sB[3][DIM];
    __shared__ float sOm[DIM * RFEAT];
    __shared__ float sRow[16][DIM];
    __shared__ float sAn[16][DIM];
    __shared__ float sK[16][33];
    __shared__ float sVv[16][33];
    __shared__ float sQf[16][33];
    __shared__ float sPK[16][RFEAT];

    int tid = threadIdx.x, lane = tid & 31, w = tid >> 5;
    for (int idx = tid; idx < DIM * DIM; idx += 512) {
        sW[0][idx] = Wq[idx]; sW[1][idx] = Wk[idx]; sW[2][idx] = Wv[idx];
    }
    for (int idx = tid; idx < DIM * RFEAT; idx += 512) sOm[idx] = omega[idx];
    if (tid < DIM) { sB[0][tid] = bq[tid]; sB[1][tid] = bk[tid]; sB[2][tid] = bv[tid]; }

    int i0 = blockIdx.x * 16;
    int i = i0 + w;
    float zk = Z[i * DIM + lane];
    __syncthreads();

    sRow[w][lane] = zk;
    __syncwarp();

    float a[3];
    #pragma unroll
    for (int p = 0; p < 3; p++) {
        float s0 = sB[p][lane], s1 = 0.f;
        #pragma unroll
        for (int k = 0; k < DIM; k += 2) {
            s0 = fmaf(sRow[w][k],     sW[p][k * DIM + lane],       s0);
            s1 = fmaf(sRow[w][k + 1], sW[p][(k + 1) * DIM + lane], s1);
        }
        a[p] = s0 + s1;
    }
    g_V[i * DIM + lane] = a[2];
    sQf[w][lane] = a[0];
    sK[w][lane]  = a[1] * KSCALE;
    sVv[w][lane] = a[2];

    #pragma unroll
    for (int p = 0; p < 2; p++) {
        float v = a[p];
        float ss = warp_sum(v * v);
        float an = v * (1.f / fmaxf(sqrtf(ss), 1e-6f));
        sAn[w][lane] = an;
        __syncwarp();
        float d0 = 0.f, d1 = 0.f, d2 = 0.f, d3 = 0.f;
        #pragma unroll
        for (int k = 0; k < DIM; k += 2) {
            float ab0 = sAn[w][k], ab1 = sAn[w][k + 1];
            float2 om0 = *(const float2*)&sOm[k * RFEAT + 2 * lane];
            float2 om1 = *(const float2*)&sOm[(k + 1) * RFEAT + 2 * lane];
            d0 = fmaf(ab0, om0.x, d0); d1 = fmaf(ab0, om0.y, d1);
            d2 = fmaf(ab1, om1.x, d2); d3 = fmaf(ab1, om1.y, d3);
        }
        float e0 = fast_ex2((d0 + d2) * L2E) * 0.125f;  // exp(d)/sqrt(r), r=64
        float e1 = fast_ex2((d1 + d3) * L2E) * 0.125f;
        float2 ph; ph.x = e0; ph.y = e1;
        if (p == 0) {
            *(float2*)&g_phiQ[i * RFEAT + 2 * lane] = ph;
            g_phiQh2[i * (RFEAT / 2) + lane] = packbf(e0, e1);
        } else {
            sPK[w][2 * lane] = e0; sPK[w][2 * lane + 1] = e1;
            g_phiKh2[i * (RFEAT / 2) + lane] = packbf(e0, e1);
        }
        __syncwarp();
    }

    __syncthreads();
    if (tid < 256) {
        // V^T bf16x2 j-pairs, q fp16x2 k-pairs
        int k = tid >> 3, p = tid & 7;
        g_VT2[k * (N_TOK / 2) + (i0 >> 1) + p] = packbf(sVv[2 * p][k], sVv[2 * p + 1][k]);
        int k2 = tid >> 4, r = tid & 15;
        g_Qh2[(i0 + r) * (DIM / 2) + k2] = packh(sQf[r][2 * k2], sQf[r][2 * k2 + 1]);
    }
    if (tid < 128) {
        // K^T k-quad entries [k4][j]
        int k4 = tid >> 4, r = tid & 15;
        g_KT4[k4 * N_TOK + i0 + r] = make_uint2(
            packh(sK[r][4 * k4 + 0], sK[r][4 * k4 + 1]),
            packh(sK[r][4 * k4 + 2], sK[r][4 * k4 + 3]));
    }

    // partial M = phiK_blk^T @ V_blk -> atomicAdd (4 outputs/thread)
    {
        int r  = tid >> 3;
        int c0 = (tid & 7) * 4;
        float m0 = 0.f, m1 = 0.f, m2 = 0.f, m3 = 0.f;
        #pragma unroll
        for (int ii = 0; ii < 16; ii++) {
            float pk = sPK[ii][r];
            m0 = fmaf(pk, sVv[ii][c0 + 0], m0);
            m1 = fmaf(pk, sVv[ii][c0 + 1], m1);
            m2 = fmaf(pk, sVv[ii][c0 + 2], m2);
            m3 = fmaf(pk, sVv[ii][c0 + 3], m3);
        }
        atomicAdd(&g_M[r * DIM + c0 + 0], m0);
        atomicAdd(&g_M[r * DIM + c0 + 1], m1);
        atomicAdd(&g_M[r * DIM + c0 + 2], m2);
        atomicAdd(&g_M[r * DIM + c0 + 3], m3);
    }
}

// ---------------------------------------------------------------------
// K3: attention; 2 supertiles per block barrier (sS is warp-private so
// only tiles/sP need block-scope ordering). Fused phi-mma (parity
// groups), fused epilogue. 1024 thr, 16 rows/block, grid 128.
// Dynamic smem (byte offsets):
//   0      sKT4 [4][8][128]uint2 32768   (k-quad rows, 1024B each)
//   32768  sVT2 [4][32][68]u32   34816 -> 67584
//   67584  sP   [4][16][128]f32  32768 -> 100352
//   100352 sS   [16][128]f32      8192 -> 108544
//   108544 sPQ  [16][64]f32       4096 -> 112640
//   112640 sWo  [32][32]f32       4096 -> 116736
//   116736 sAcc [32][32]f32       4096 -> 120832
//   120832 sVec [6][32]f32         768 -> 121600
//   121600 sb1  [128]f32           512 -> 122112
//   122112 sZ1  [16][32]f32       2048 -> 124160
// Epilogue overlay in [0, 67584): sM@0, sW1@8192, sW2@24576, sH@40960.
// ---------------------------------------------------------------------
#define K3_SMEM_BYTES 124160

__device__ __forceinline__ void k3_stage(int t, int tid, unsigned base)
{
    if (tid < 512) {
        int k4 = tid >> 6, c = tid & 63;
        CP_ASYNC16(base + (unsigned)((t & 3) * 8192 + k4 * 1024 + c * 16),
                   g_KT4 + k4 * N_TOK + t * 128 + c * 2);
    } else {
        int idx = tid - 512;
        int row = idx >> 4, c = idx & 15;
        CP_ASYNC16(base + (unsigned)(32768 + (t & 3) * 8704 + row * 272 + c * 16),
                   g_VT2 + row * (N_TOK / 2) + t * 64 + c * 4);
    }
}

__global__ void __launch_bounds__(1024, 1) k3_attn(
    const int* __restrict__ mask,
    const float* __restrict__ Wo, const float* __restrict__ bo,
    const float* __restrict__ Z,
    const float* __restrict__ W1, const float* __restrict__ b1,
    const float* __restrict__ W2, const float* __restrict__ b2,
    const float* __restrict__ g1, const float* __restrict__ be1,
    const float* __restrict__ g2, const float* __restrict__ be2,
    float* __restrict__ out)
{
    extern __shared__ char sm_raw[];
    unsigned smem_base = (unsigned)__cvta_generic_to_shared(sm_raw);
    float* sP   = (float*)(sm_raw + 67584);
    float* sS   = (float*)(sm_raw + 100352);
    float* sPQ  = (float*)(sm_raw + 108544);
    float* sWo  = (float*)(sm_raw + 112640);
    float* sAcc = (float*)(sm_raw + 116736);
    float* sVec = (float*)(sm_raw + 120832);
    float* sb1  = (float*)(sm_raw + 121600);
    float* sZ1  = (float*)(sm_raw + 122112);
    // epilogue overlay
    float* sM   = (float*)(sm_raw);
    float* sW1  = (float*)(sm_raw + 8192);
    float* sW2  = (float*)(sm_raw + 24576);
    float* sH   = (float*)(sm_raw + 40960);

    int tid = threadIdx.x, lane = tid & 31, w = tid >> 5;
    int r16 = w >> 1, h = w & 1;
    int g   = lane >> 2, tig = lane & 3;       // mma fragment coords
    int wt  = w & 15;                          // mma n8-tile index
    int i0 = blockIdx.x * 16;
    int i  = i0 + r16;

    // stage persistent data
    sPQ[tid] = g_phiQ[i0 * RFEAT + tid];
    for (int idx = tid; idx < DIM * DIM; idx += 1024) sWo[idx] = Wo[idx];
    if (tid < HDIM) sb1[tid] = b1[tid];
    if (tid < DIM) {
        sVec[tid] = bo[tid];        sVec[32 + tid] = b2[tid];
        sVec[64 + tid] = g1[tid];   sVec[96 + tid] = be1[tid];
        sVec[128 + tid] = g2[tid];  sVec[160 + tid] = be2[tid];
    }

    // q fp16x2 k-pairs: loop-invariant registers
    __half2 qreg[16];
    {
        const uint4* qp = (const uint4*)(g_Qh2 + i * (DIM / 2));
        #pragma unroll
        for (int u = 0; u < 4; u++) {
            uint4 t4 = qp[u];
            qreg[u * 4 + 0] = u2h(t4.x); qreg[u * 4 + 1] = u2h(t4.y);
            qreg[u * 4 + 2] = u2h(t4.z); qreg[u * 4 + 3] = u2h(t4.w);
        }
    }

    // A-fragments (phiQ rows i0..i0+15): loop-invariant
    unsigned afrag[16];
    #pragma unroll
    for (int ks = 0; ks < 4; ks++) {
        int kp = ks * 8 + tig;
        afrag[ks * 4 + 0] = g_phiQh2[(i0 + g)     * 32 + kp];
        afrag[ks * 4 + 1] = g_phiQh2[(i0 + g + 8) * 32 + kp];
        afrag[ks * 4 + 2] = g_phiQh2[(i0 + g)     * 32 + kp + 4];
        afrag[ks * 4 + 3] = g_phiQh2[(i0 + g + 8) * 32 + kp + 4];
    }

    const int2* mrow2 = (const int2*)(mask + (size_t)i * N_TOK);
    float acc = 0.f;
    int jb = h * 64 + 2 * lane;
    int vidx = h * 32 + lane;

    k3_stage(0, tid, smem_base);
    k3_stage(1, tid, smem_base);
    CP_COMMIT();

    // prologue mma: group A -> P(0), group B -> P(1)
    {
        int tn = (w < 16) ? 0 : 1;
        int jn0 = tn * 128 + wt * 8;
        float d0 = 0.f, d1 = 0.f, d2 = 0.f, d3 = 0.f;
        #pragma unroll
        for (int ks = 0; ks < 4; ks++) {
            int kp = ks * 8 + tig;
            unsigned b0 = g_phiKh2[(jn0 + g) * 32 + kp];
            unsigned b1 = g_phiKh2[(jn0 + g) * 32 + kp + 4];
            asm volatile(
                "mma.sync.aligned.m16n8k16.row.col.f32.bf16.bf16.f32 "
                "{%0,%1,%2,%3}, {%4,%5,%6,%7}, {%8,%9}, {%0,%1,%2,%3};"
                : "+f"(d0), "+f"(d1), "+f"(d2), "+f"(d3)
                : "r"(afrag[ks*4+0]), "r"(afrag[ks*4+1]),
                  "r"(afrag[ks*4+2]), "r"(afrag[ks*4+3]), "r"(b0), "r"(b1));
        }
        float* sPb = sP + tn * 2048;
        int jc = wt * 8 + 2 * tig;
        *(float2*)&sPb[g * 128 + jc]       = make_float2(d0, d1);
        *(float2*)&sPb[(g + 8) * 128 + jc] = make_float2(d2, d3);
    }

    #pragma unroll 1
    for (int tb = 0; tb < NSUP / 2; tb++) {
        int t0 = 2 * tb, t1 = 2 * tb + 1;
        CP_WAIT0();
        __syncthreads();
        if (t0 + 2 < NSUP) {
            k3_stage(t0 + 2, tid, smem_base);
            k3_stage(t1 + 2, tid, smem_base);
            CP_COMMIT();
        }

        // pipelined mma: group A -> P(t0+2), group B -> P(t1+2)
        if (t0 + 2 < NSUP) {
            int tn = (w < 16) ? (t0 + 2) : (t1 + 2);
            int jn0 = tn * 128 + wt * 8;
            float d0 = 0.f, d1 = 0.f, d2 = 0.f, d3 = 0.f;
            #pragma unroll
            for (int ks = 0; ks < 4; ks++) {
                int kp = ks * 8 + tig;
                unsigned b0 = g_phiKh2[(jn0 + g) * 32 + kp];
                unsigned b1 = g_phiKh2[(jn0 + g) * 32 + kp + 4];
                asm volatile(
                    "mma.sync.aligned.m16n8k16.row.col.f32.bf16.bf16.f32 "
                    "{%0,%1,%2,%3}, {%4,%5,%6,%7}, {%8,%9}, {%0,%1,%2,%3};"
                    : "+f"(d0), "+f"(d1), "+f"(d2), "+f"(d3)
                    : "r"(afrag[ks*4+0]), "r"(afrag[ks*4+1]),
                      "r"(afrag[ks*4+2]), "r"(afrag[ks*4+3]), "r"(b0), "r"(b1));
            }
            float* sPb = sP + (tn & 3) * 2048;
            int jc = wt * 8 + 2 * tig;
            *(float2*)&sPb[g * 128 + jc]       = make_float2(d0, d1);
            *(float2*)&sPb[(g + 8) * 128 + jc] = make_float2(d2, d3);
        }

        // ================= supertile t0 =================
        {
            const uint4* KT4 = (const uint4*)(sm_raw + (t0 & 3) * 8192);
            int2 mv = mrow2[t0 * 64 + vidx];
            __half2 aA0 = __floats2half2_rn(0.f, 0.f);
            __half2 aA1 = aA0, aB0 = aA0, aB1 = aA0;
            #pragma unroll
            for (int k4 = 0; k4 < 8; k4++) {
                uint4 kk = KT4[k4 * 64 + vidx];
                aA0 = __hadd2(aA0, h2ex2(__hmul2(qreg[2 * k4],     u2h(kk.x))));
                aA1 = __hadd2(aA1, h2ex2(__hmul2(qreg[2 * k4 + 1], u2h(kk.y))));
                aB0 = __hadd2(aB0, h2ex2(__hmul2(qreg[2 * k4],     u2h(kk.z))));
                aB1 = __hadd2(aB1, h2ex2(__hmul2(qreg[2 * k4 + 1], u2h(kk.w))));
            }
            float eA = (__low2float(aA0) + __high2float(aA0)) + (__low2float(aA1) + __high2float(aA1));
            float eB = (__low2float(aB0) + __high2float(aB0)) + (__low2float(aB1) + __high2float(aB1));
            float2 Pw = *(const float2*)&sP[(t0 & 3) * 2048 + r16 * 128 + jb];
            float2 sv;
            sv.x = (mv.x == 0) ? (eA - Pw.x) : 0.f;
            sv.y = (mv.y == 0) ? (eB - Pw.y) : 0.f;
            *(float2*)&sS[r16 * 128 + jb] = sv;
            __syncwarp();
            const unsigned* VT = (const unsigned*)(sm_raw + 32768 + (t0 & 3) * 8704)
                                 + lane * 68 + h * 32;
            const float4* SS = (const float4*)&sS[r16 * 128 + h * 64];
            #pragma unroll
            for (int j8 = 0; j8 < 8; j8++) {
                uint4 v = *(const uint4*)(VT + j8 * 4);
                float4 s0 = SS[2 * j8], s1 = SS[2 * j8 + 1];
                acc = fmaf(s0.x, BFLO(v.x), acc); acc = fmaf(s0.y, BFHI(v.x), acc);
                acc = fmaf(s0.z, BFLO(v.y), acc); acc = fmaf(s0.w, BFHI(v.y), acc);
                acc = fmaf(s1.x, BFLO(v.z), acc); acc = fmaf(s1.y, BFHI(v.z), acc);
                acc = fmaf(s1.z, BFLO(v.w), acc); acc = fmaf(s1.w, BFHI(v.w), acc);
            }
        }
        __syncwarp();   // AV(t0) reads done before sS overwrite

        // ================= supertile t1 =================
        {
            const uint4* KT4 = (const uint4*)(sm_raw + (t1 & 3) * 8192);
            int2 mv = mrow2[t1 * 64 + vidx];
            __half2 aA0 = __floats2half2_rn(0.f, 0.f);
            __half2 aA1 = aA0, aB0 = aA0, aB1 = aA0;
            #pragma unroll
            for (int k4 = 0; k4 < 8; k4++) {
                uint4 kk = KT4[k4 * 64 + vidx];
                aA0 = __hadd2(aA0, h2ex2(__hmul2(qreg[2 * k4],     u2h(kk.x))));
                aA1 = __hadd2(aA1, h2ex2(__hmul2(qreg[2 * k4 + 1], u2h(kk.y))));
                aB0 = __hadd2(aB0, h2ex2(__hmul2(qreg[2 * k4],     u2h(kk.z))));
                aB1 = __hadd2(aB1, h2ex2(__hmul2(qreg[2 * k4 + 1], u2h(kk.w))));
            }
            float eA = (__low2float(aA0) + __high2float(aA0)) + (__low2float(aA1) + __high2float(aA1));
            float eB = (__low2float(aB0) + __high2float(aB0)) + (__low2float(aB1) + __high2float(aB1));
            float2 Pw = *(const float2*)&sP[(t1 & 3) * 2048 + r16 * 128 + jb];
            float2 sv;
            sv.x = (mv.x == 0) ? (eA - Pw.x) : 0.f;
            sv.y = (mv.y == 0) ? (eB - Pw.y) : 0.f;
            *(float2*)&sS[r16 * 128 + jb] = sv;
            __syncwarp();
            const unsigned* VT = (const unsigned*)(sm_raw + 32768 + (t1 & 3) * 8704)
                                 + lane * 68 + h * 32;
            const float4* SS = (const float4*)&sS[r16 * 128 + h * 64];
            #pragma unroll
            for (int j8 = 0; j8 < 8; j8++) {
                uint4 v = *(const uint4*)(VT + j8 * 4);
                float4 s0 = SS[2 * j8], s1 = SS[2 * j8 + 1];
                acc = fmaf(s0.x, BFLO(v.x), acc); acc = fmaf(s0.y, BFHI(v.x), acc);
                acc = fmaf(s0.z, BFLO(v.y), acc); acc = fmaf(s0.w, BFHI(v.y), acc);
                acc = fmaf(s1.x, BFLO(v.z), acc); acc = fmaf(s1.y, BFHI(v.z), acc);
                acc = fmaf(s1.z, BFLO(v.w), acc); acc = fmaf(s1.w, BFHI(v.w), acc);
            }
        }
        __syncwarp();
    }

    // ---- epilogue ----
    __syncthreads();
    for (int idx = tid; idx < RFEAT * DIM; idx += 1024) sM[idx] = g_M[idx];
    for (int idx = tid; idx < DIM * HDIM; idx += 1024) { sW1[idx] = W1[idx]; sW2[idx] = W2[idx]; }
    sAcc[w * 32 + lane] = acc;
    __syncthreads();

    if (h == 0) {
        float lr = 0.f;
        #pragma unroll
        for (int r = 0; r < RFEAT; r++) lr = fmaf(sPQ[r16 * RFEAT + r], sM[r * DIM + lane], lr);

        float attn = sAcc[w * 32 + lane] + sAcc[(w + 1) * 32 + lane] + lr;
        float denom = fmaxf(warp_sum(attn), 1e-6f);
        float a = attn / denom;

        sAcc[w * 32 + lane] = a;
        __syncwarp();
        float o = sVec[lane];   // bo
        #pragma unroll
        for (int c = 0; c < DIM; c++) o = fmaf(sAcc[w * 32 + c], sWo[c * DIM + lane], o);

        // LN1
        float x = Z[i * DIM + lane] + o;
        float mu = warp_sum(x) * (1.f / 32.f);
        float dd = x - mu;
        float var = warp_sum(dd * dd) * (1.f / 32.f);
        float z1 = dd * rsqrtf(var + 1e-5f) * sVec[64 + lane] + sVec[96 + lane];
        sZ1[r16 * DIM + lane] = z1;
        __syncwarp();

        // FFN up + relu
        float hh[4];
        #pragma unroll
        for (int u = 0; u < 4; u++) hh[u] = sb1[lane + u * 32];
        #pragma unroll
        for (int k = 0; k < DIM; k++) {
            float zk = sZ1[r16 * DIM + k];
            #pragma unroll
            for (int u = 0; u < 4; u++) hh[u] = fmaf(zk, sW1[k * HDIM + lane + u * 32], hh[u]);
        }
        #pragma unroll
        for (int u = 0; u < 4; u++) sH[r16 * HDIM + lane + u * 32] = fmaxf(hh[u], 0.f);
        __syncwarp();

        // FFN down
        float o0 = sVec[32 + lane], o1 = 0.f, o2 = 0.f, o3 = 0.f;
        #pragma unroll
        for (int j = 0; j < HDIM; j += 4) {
            o0 = fmaf(sH[r16 * HDIM + j + 0], sW2[(j + 0) * DIM + lane], o0);
            o1 = fmaf(sH[r16 * HDIM + j + 1], sW2[(j + 1) * DIM + lane], o1);
            o2 = fmaf(sH[r16 * HDIM + j + 2], sW2[(j + 2) * DIM + lane], o2);
            o3 = fmaf(sH[r16 * HDIM + j + 3], sW2[(j + 3) * DIM + lane], o3);
        }
        float y = z1 + ((o0 + o1) + (o2 + o3));

        // LN2
        float mu2 = warp_sum(y) * (1.f / 32.f);
        float dd2 = y - mu2;
        float var2 = warp_sum(dd2 * dd2) * (1.f / 32.f);
        out[i * DIM + lane] = dd2 * rsqrtf(var2 + 1e-5f) * sVec[128 + lane] + sVec[160 + lane];
    }
}

// ---------------------------------------------------------------------
extern "C" void kernel_launch(void* const* d_in, const int* in_sizes, int n_in,
                              void* d_out, int out_size)
{
    const float* Z    = (const float*)d_in[0];
    const int*   mask = (const int*)  d_in[1];
    const float* Wq = (const float*)d_in[2],  *bq = (const float*)d_in[3];
    const float* Wk = (const float*)d_in[4],  *bk = (const float*)d_in[5];
    const float* Wv = (const float*)d_in[6],  *bv = (const float*)d_in[7];
    const float* Wo = (const float*)d_in[8],  *bo = (const float*)d_in[9];
    const float* W1 = (const float*)d_in[10], *b1 = (const float*)d_in[11];
    const float* W2 = (const float*)d_in[12], *b2 = (const float*)d_in[13];
    const float* g1 = (const float*)d_in[14], *be1 = (const float*)d_in[15];
    const float* g2 = (const float*)d_in[16], *be2 = (const float*)d_in[17];
    const float* omega = (const float*)d_in[18];

    cudaFuncSetAttribute(k3_attn, cudaFuncAttributeMaxDynamicSharedMemorySize, K3_SMEM_BYTES);

    void* mptr = nullptr;
    cudaGetSymbolAddress(&mptr, g_M);
    cudaMemsetAsync(mptr, 0, RFEAT * DIM * sizeof(float));

    k1_proj<<<N_TOK / 16, 512>>>(Z, Wq, bq, Wk, bk, Wv, bv, omega);
    k3_attn<<<N_TOK / 16, 1024, K3_SMEM_BYTES>>>(mask, Wo, bo, Z,
                                                 W1, b1, W2, b2,
                                                 g1, be1, g2, be2, (float*)d_out);
}

// round 17
// speedup vs baseline: 1.2231x; 1.1721x over previous
#include <cuda_runtime.h>
#include <cuda_bf16.h>
#include <cuda_fp16.h>
#include <cstdint>

#define N_TOK 2048
#define DIM   32
#define RFEAT 64
#define HDIM  128
#define NSUP  (N_TOK / 128)     // 16 supertiles of 128 j

// ---------- scratch (device globals; no allocation allowed) ----------
__device__ __align__(16) float    g_V[N_TOK * DIM];
__device__ __align__(16) float    g_phiQ[N_TOK * RFEAT];
__device__ __align__(16) unsigned g_phiQh2[N_TOK * (RFEAT / 2)]; // row-major bf16x2 r-pairs
__device__ __align__(16) unsigned g_phiKh2[N_TOK * (RFEAT / 2)];
__device__ __align__(16) uint2    g_KT4[(DIM / 4) * N_TOK];      // [k4][j]: 4 fp16 k-values per col
__device__ __align__(16) unsigned g_Qh2[N_TOK * (DIM / 2)];      // [i][k2] fp16x2 k-pairs
__device__ __align__(16) unsigned g_VT2[DIM * (N_TOK / 2)];      // [c][j2] bf16x2 j-pairs
__device__ __align__(16) float    g_M[RFEAT * DIM];              // phi_K^T @ V (atomic accum)

__device__ __forceinline__ float fast_ex2(float x) {
    float y;
    asm("ex2.approx.ftz.f32 %0, %1;" : "=f"(y) : "f"(x));
    return y;
}
__device__ __forceinline__ __half2 h2ex2(__half2 x) {
    __half2 y;
    asm("ex2.approx.f16x2 %0, %1;" : "=r"(*(unsigned*)&y) : "r"(*(unsigned*)&x));
    return y;
}
__device__ __forceinline__ __half2 u2h(unsigned u) { return *reinterpret_cast<__half2*>(&u); }

__device__ __forceinline__ float warp_sum(float v) {
    v += __shfl_xor_sync(0xffffffffu, v, 16);
    v += __shfl_xor_sync(0xffffffffu, v, 8);
    v += __shfl_xor_sync(0xffffffffu, v, 4);
    v += __shfl_xor_sync(0xffffffffu, v, 2);
    v += __shfl_xor_sync(0xffffffffu, v, 1);
    return v;
}
__device__ __forceinline__ unsigned packbf(float a, float b) {
    __nv_bfloat162 h = __floats2bfloat162_rn(a, b);
    return *reinterpret_cast<unsigned*>(&h);
}
__device__ __forceinline__ unsigned packh(float a, float b) {
    __half2 h = __floats2half2_rn(a, b);
    return *reinterpret_cast<unsigned*>(&h);
}
#define BFLO(u) __uint_as_float((u) << 16)
#define BFHI(u) __uint_as_float((u) & 0xffff0000u)

#define CP_ASYNC16(dst_s, src_g) \
    asm volatile("cp.async.cg.shared.global [%0], [%1], 16;" :: "r"(dst_s), "l"(src_g))
#define CP_COMMIT() asm volatile("cp.async.commit_group;")
#define CP_WAIT0()  asm volatile("cp.async.wait_group 0;" ::: "memory")

#define MMA_BF16(d0,d1,d2,d3,a0,a1,a2,a3,b0,b1) \
    asm volatile( \
        "mma.sync.aligned.m16n8k16.row.col.f32.bf16.bf16.f32 " \
        "{%0,%1,%2,%3}, {%4,%5,%6,%7}, {%8,%9}, {%0,%1,%2,%3};" \
        : "+f"(d0), "+f"(d1), "+f"(d2), "+f"(d3) \
        : "r"(a0), "r"(a1), "r"(a2), "r"(a3), "r"(b0), "r"(b1))

#define L2E    1.4426950408889634f
#define KSCALE ((float)(1.4426950408889634 / 5.6568542494923806)) // log2e/sqrt(32)

// ---------------------------------------------------------------------
// K1: warp-per-row QKV + norms + random features + partial phiK^T V
// (atomicAdd into g_M). 16 rows/block, 512 threads, grid 128.
// ---------------------------------------------------------------------
__global__ void __launch_bounds__(512) k1_proj(const float* __restrict__ Z,
                        const float* __restrict__ Wq, const float* __restrict__ bq,
                        const float* __restrict__ Wk, const float* __restrict__ bk,
                        const float* __restrict__ Wv, const float* __restrict__ bv,
                        const float* __restrict__ omega)
{
    __shared__ float sW[3][DIM * DIM];
    __shared__ float sB[3][DIM];
    __shared__ float sOm[DIM * RFEAT];
    __shared__ float sRow[16][DIM];
    __shared__ float sAn[16][DIM];
    __shared__ float sK[16][33];
    __shared__ float sVv[16][33];
    __shared__ float sQf[16][33];
    __shared__ float sPK[16][RFEAT];

    int tid = threadIdx.x, lane = tid & 31, w = tid >> 5;
    for (int idx = tid; idx < DIM * DIM; idx += 512) {
        sW[0][idx] = Wq[idx]; sW[1][idx] = Wk[idx]; sW[2][idx] = Wv[idx];
    }
    for (int idx = tid; idx < DIM * RFEAT; idx += 512) sOm[idx] = omega[idx];
    if (tid < DIM) { sB[0][tid] = bq[tid]; sB[1][tid] = bk[tid]; sB[2][tid] = bv[tid]; }

    int i0 = blockIdx.x * 16;
    int i = i0 + w;
    float zk = Z[i * DIM + lane];
    __syncthreads();

    sRow[w][lane] = zk;
    __syncwarp();

    float a[3];
    #pragma unroll
    for (int p = 0; p < 3; p++) {
        float s0 = sB[p][lane], s1 = 0.f;
        #pragma unroll
        for (int k = 0; k < DIM; k += 2) {
            s0 = fmaf(sRow[w][k],     sW[p][k * DIM + lane],       s0);
            s1 = fmaf(sRow[w][k + 1], sW[p][(k + 1) * DIM + lane], s1);
        }
        a[p] = s0 + s1;
    }
    g_V[i * DIM + lane] = a[2];
    sQf[w][lane] = a[0];
    sK[w][lane]  = a[1] * KSCALE;
    sVv[w][lane] = a[2];

    #pragma unroll
    for (int p = 0; p < 2; p++) {
        float v = a[p];
        float ss = warp_sum(v * v);
        float an = v * (1.f / fmaxf(sqrtf(ss), 1e-6f));
        sAn[w][lane] = an;
        __syncwarp();
        float d0 = 0.f, d1 = 0.f, d2 = 0.f, d3 = 0.f;
        #pragma unroll
        for (int k = 0; k < DIM; k += 2) {
            float ab0 = sAn[w][k], ab1 = sAn[w][k + 1];
            float2 om0 = *(const float2*)&sOm[k * RFEAT + 2 * lane];
            float2 om1 = *(const float2*)&sOm[(k + 1) * RFEAT + 2 * lane];
            d0 = fmaf(ab0, om0.x, d0); d1 = fmaf(ab0, om0.y, d1);
            d2 = fmaf(ab1, om1.x, d2); d3 = fmaf(ab1, om1.y, d3);
        }
        float e0 = fast_ex2((d0 + d2) * L2E) * 0.125f;  // exp(d)/sqrt(r), r=64
        float e1 = fast_ex2((d1 + d3) * L2E) * 0.125f;
        float2 ph; ph.x = e0; ph.y = e1;
        if (p == 0) {
            *(float2*)&g_phiQ[i * RFEAT + 2 * lane] = ph;
            g_phiQh2[i * (RFEAT / 2) + lane] = packbf(e0, e1);
        } else {
            sPK[w][2 * lane] = e0; sPK[w][2 * lane + 1] = e1;
            g_phiKh2[i * (RFEAT / 2) + lane] = packbf(e0, e1);
        }
        __syncwarp();
    }

    __syncthreads();
    if (tid < 256) {
        // V^T bf16x2 j-pairs, q fp16x2 k-pairs
        int k = tid >> 3, p = tid & 7;
        g_VT2[k * (N_TOK / 2) + (i0 >> 1) + p] = packbf(sVv[2 * p][k], sVv[2 * p + 1][k]);
        int k2 = tid >> 4, r = tid & 15;
        g_Qh2[(i0 + r) * (DIM / 2) + k2] = packh(sQf[r][2 * k2], sQf[r][2 * k2 + 1]);
    }
    if (tid < 128) {
        // K^T k-quad entries [k4][j]
        int k4 = tid >> 4, r = tid & 15;
        g_KT4[k4 * N_TOK + i0 + r] = make_uint2(
            packh(sK[r][4 * k4 + 0], sK[r][4 * k4 + 1]),
            packh(sK[r][4 * k4 + 2], sK[r][4 * k4 + 3]));
    }

    // partial M = phiK_blk^T @ V_blk -> atomicAdd (4 outputs/thread)
    {
        int r  = tid >> 3;
        int c0 = (tid & 7) * 4;
        float m0 = 0.f, m1 = 0.f, m2 = 0.f, m3 = 0.f;
        #pragma unroll
        for (int ii = 0; ii < 16; ii++) {
            float pk = sPK[ii][r];
            m0 = fmaf(pk, sVv[ii][c0 + 0], m0);
            m1 = fmaf(pk, sVv[ii][c0 + 1], m1);
            m2 = fmaf(pk, sVv[ii][c0 + 2], m2);
            m3 = fmaf(pk, sVv[ii][c0 + 3], m3);
        }
        atomicAdd(&g_M[r * DIM + c0 + 0], m0);
        atomicAdd(&g_M[r * DIM + c0 + 1], m1);
        atomicAdd(&g_M[r * DIM + c0 + 2], m2);
        atomicAdd(&g_M[r * DIM + c0 + 3], m3);
    }
}

// ---------------------------------------------------------------------
// K3: attention with BOTH GEMM-like parts on mma.sync:
//   - phi term P = phiQ@phiK^T (parity groups, lookahead 2, 4-buf sP)
//   - AV: scores packed bf16x2 -> per-warp (ks,nc) mma fragment,
//     accumulated in registers across all supertiles, deferred 1 iter.
// exp path: fp16x2 dual-ex2 on k-quad LDS.128 tiles (unchanged).
// 1024 thr, 16 rows/block, grid 128, 2 supertiles per barrier.
// Dynamic smem (byte offsets):
//   0      sKT4 [4][8][128]uint2 32768
//   32768  sVT  [6][32][68]u32   52224 -> 84992
//   84992  sP   [4][16][128]f32  32768 -> 117760
//   117760 sS2  [4][16][68]u32   17408 -> 135168  (bf16x2 scores, pad 68)
//   135168 sPQ  [16][64]f32       4096 -> 139264
//   139264 sWo  [32][32]f32       4096 -> 143360
//   143360 sVec [6][32]f32         768 -> 144128
//   144128 sb1  [128]f32           512 -> 144640
//   144640 sZ1  [16][32]f32       2048 -> 146688
// Epilogue overlay in [0, 84992): sM@0, sW1@8192, sW2@24576, sH@40960,
//   sRed@49152 (8*16*32 f32 = 16384) -> 65536.
// ---------------------------------------------------------------------
#define K3_SMEM_BYTES 146688

__device__ __forceinline__ void k3_stage(int t, int tid, unsigned base)
{
    if (tid < 512) {
        int k4 = tid >> 6, c = tid & 63;
        CP_ASYNC16(base + (unsigned)((t & 3) * 8192 + k4 * 1024 + c * 16),
                   g_KT4 + k4 * N_TOK + t * 128 + c * 2);
    } else {
        int idx = tid - 512;
        int row = idx >> 4, c = idx & 15;
        CP_ASYNC16(base + (unsigned)(32768 + (t % 6) * 8704 + row * 272 + c * 16),
                   g_VT2 + row * (N_TOK / 2) + t * 64 + c * 4);
    }
}

__global__ void __launch_bounds__(1024, 1) k3_attn(
    const int* __restrict__ mask,
    const float* __restrict__ Wo, const float* __restrict__ bo,
    const float* __restrict__ Z,
    const float* __restrict__ W1, const float* __restrict__ b1,
    const float* __restrict__ W2, const float* __restrict__ b2,
    const float* __restrict__ g1, const float* __restrict__ be1,
    const float* __restrict__ g2, const float* __restrict__ be2,
    float* __restrict__ out)
{
    extern __shared__ char sm_raw[];
    unsigned smem_base = (unsigned)__cvta_generic_to_shared(sm_raw);
    float*    sP   = (float*)(sm_raw + 84992);
    unsigned* sS2  = (unsigned*)(sm_raw + 117760);
    float*    sPQ  = (float*)(sm_raw + 135168);
    float*    sWo  = (float*)(sm_raw + 139264);
    float*    sVec = (float*)(sm_raw + 143360);
    float*    sb1  = (float*)(sm_raw + 144128);
    float*    sZ1  = (float*)(sm_raw + 144640);
    // epilogue overlay
    float* sM   = (float*)(sm_raw);
    float* sW1  = (float*)(sm_raw + 8192);
    float* sW2  = (float*)(sm_raw + 24576);
    float* sH   = (float*)(sm_raw + 40960);
    float* sRed = (float*)(sm_raw + 49152);

    int tid = threadIdx.x, lane = tid & 31, w = tid >> 5;
    int r16 = w >> 1, h = w & 1;
    int g   = lane >> 2, tig = lane & 3;       // mma fragment coords
    int wt  = w & 15;                          // phi-mma n8-tile index
    int ks  = w & 7,  nc = w >> 3;             // AV-mma fragment (k-step, n-tile)
    int i0 = blockIdx.x * 16;
    int i  = i0 + r16;

    // stage persistent data
    sPQ[tid] = g_phiQ[i0 * RFEAT + tid];
    for (int idx = tid; idx < DIM * DIM; idx += 1024) sWo[idx] = Wo[idx];
    if (tid < HDIM) sb1[tid] = b1[tid];
    if (tid < DIM) {
        sVec[tid] = bo[tid];        sVec[32 + tid] = b2[tid];
        sVec[64 + tid] = g1[tid];   sVec[96 + tid] = be1[tid];
        sVec[128 + tid] = g2[tid];  sVec[160 + tid] = be2[tid];
    }

    // q fp16x2 k-pairs: loop-invariant registers
    __half2 qreg[16];
    {
        const uint4* qp = (const uint4*)(g_Qh2 + i * (DIM / 2));
        #pragma unroll
        for (int u = 0; u < 4; u++) {
            uint4 t4 = qp[u];
            qreg[u * 4 + 0] = u2h(t4.x); qreg[u * 4 + 1] = u2h(t4.y);
            qreg[u * 4 + 2] = u2h(t4.z); qreg[u * 4 + 3] = u2h(t4.w);
        }
    }

    // A-fragments for phi-mma (phiQ rows i0..i0+15): loop-invariant
    unsigned afrag[16];
    #pragma unroll
    for (int kss = 0; kss < 4; kss++) {
        int kp = kss * 8 + tig;
        afrag[kss * 4 + 0] = g_phiQh2[(i0 + g)     * 32 + kp];
        afrag[kss * 4 + 1] = g_phiQh2[(i0 + g + 8) * 32 + kp];
        afrag[kss * 4 + 2] = g_phiQh2[(i0 + g)     * 32 + kp + 4];
        afrag[kss * 4 + 3] = g_phiQh2[(i0 + g + 8) * 32 + kp + 4];
    }

    const int2* mrow2 = (const int2*)(mask + (size_t)i * N_TOK);
    int jb = h * 64 + 2 * lane;
    int vidx = h * 32 + lane;
    int spair = h * 32 + lane;                 // score pair index within row

    // AV accumulator fragment (rows g/g+8, cols nc*8+2tig..+1)
    float av0 = 0.f, av1 = 0.f, av2 = 0.f, av3 = 0.f;

    k3_stage(0, tid, smem_base);
    k3_stage(1, tid, smem_base);
    CP_COMMIT();

    // prologue phi-mma: group A -> P(0), group B -> P(1)
    {
        int tn = (w < 16) ? 0 : 1;
        int jn0 = tn * 128 + wt * 8;
        float d0 = 0.f, d1 = 0.f, d2 = 0.f, d3 = 0.f;
        #pragma unroll
        for (int kss = 0; kss < 4; kss++) {
            int kp = kss * 8 + tig;
            unsigned b0 = g_phiKh2[(jn0 + g) * 32 + kp];
            unsigned b1 = g_phiKh2[(jn0 + g) * 32 + kp + 4];
            MMA_BF16(d0, d1, d2, d3,
                     afrag[kss*4+0], afrag[kss*4+1], afrag[kss*4+2], afrag[kss*4+3],
                     b0, b1);
        }
        float* sPb = sP + tn * 2048;
        int jc = wt * 8 + 2 * tig;
        *(float2*)&sPb[g * 128 + jc]       = make_float2(d0, d1);
        *(float2*)&sPb[(g + 8) * 128 + jc] = make_float2(d2, d3);
    }

    #pragma unroll 1
    for (int tb = 0; tb < NSUP / 2; tb++) {
        int t0 = 2 * tb, t1 = 2 * tb + 1;
        CP_WAIT0();
        __syncthreads();   // tiles(t0,t1), sP ready; prev sS2 scores visible
        if (t0 + 2 < NSUP) {
            k3_stage(t0 + 2, tid, smem_base);
            k3_stage(t1 + 2, tid, smem_base);
            CP_COMMIT();
        }

        // phi-mma: group A -> P(t0+2), group B -> P(t1+2)
        if (t0 + 2 < NSUP) {
            int tn = (w < 16) ? (t0 + 2) : (t1 + 2);
            int jn0 = tn * 128 + wt * 8;
            float d0 = 0.f, d1 = 0.f, d2 = 0.f, d3 = 0.f;
            #pragma unroll
            for (int kss = 0; kss < 4; kss++) {
                int kp = kss * 8 + tig;
                unsigned b0 = g_phiKh2[(jn0 + g) * 32 + kp];
                unsigned b1 = g_phiKh2[(jn0 + g) * 32 + kp + 4];
                MMA_BF16(d0, d1, d2, d3,
                         afrag[kss*4+0], afrag[kss*4+1], afrag[kss*4+2], afrag[kss*4+3],
                         b0, b1);
            }
            float* sPb = sP + (tn & 3) * 2048;
            int jc = wt * 8 + 2 * tig;
            *(float2*)&sPb[g * 128 + jc]       = make_float2(d0, d1);
            *(float2*)&sPb[(g + 8) * 128 + jc] = make_float2(d2, d3);
        }

        // deferred AV-mma for (t0-2, t1-2): scores from prev iteration
        if (tb > 0) {
            #pragma unroll
            for (int u = 0; u < 2; u++) {
                int tp = t0 - 2 + u;
                const unsigned* Sb = sS2 + (tp & 3) * 1088;              // 16*68
                const unsigned* Vb = (const unsigned*)(sm_raw + 32768 + (tp % 6) * 8704);
                unsigned a0 = Sb[g * 68 + ks * 8 + tig];
                unsigned a1 = Sb[(g + 8) * 68 + ks * 8 + tig];
                unsigned a2 = Sb[g * 68 + ks * 8 + tig + 4];
                unsigned a3 = Sb[(g + 8) * 68 + ks * 8 + tig + 4];
                unsigned b0 = Vb[(nc * 8 + g) * 68 + ks * 8 + tig];
                unsigned b1 = Vb[(nc * 8 + g) * 68 + ks * 8 + tig + 4];
                MMA_BF16(av0, av1, av2, av3, a0, a1, a2, a3, b0, b1);
            }
        }

        // exp(t0), exp(t1) -> bf16x2 scores in sS2
        #pragma unroll
        for (int u = 0; u < 2; u++) {
            int t = t0 + u;
            const uint4* KT4 = (const uint4*)(sm_raw + (t & 3) * 8192);
            int2 mv = mrow2[t * 64 + vidx];
            __half2 aA0 = __floats2half2_rn(0.f, 0.f);
            __half2 aA1 = aA0, aB0 = aA0, aB1 = aA0;
            #pragma unroll
            for (int k4 = 0; k4 < 8; k4++) {
                uint4 kk = KT4[k4 * 64 + vidx];
                aA0 = __hadd2(aA0, h2ex2(__hmul2(qreg[2 * k4],     u2h(kk.x))));
                aA1 = __hadd2(aA1, h2ex2(__hmul2(qreg[2 * k4 + 1], u2h(kk.y))));
                aB0 = __hadd2(aB0, h2ex2(__hmul2(qreg[2 * k4],     u2h(kk.z))));
                aB1 = __hadd2(aB1, h2ex2(__hmul2(qreg[2 * k4 + 1], u2h(kk.w))));
            }
            float eA = (__low2float(aA0) + __high2float(aA0)) + (__low2float(aA1) + __high2float(aA1));
            float eB = (__low2float(aB0) + __high2float(aB0)) + (__low2float(aB1) + __high2float(aB1));
            float2 Pw = *(const float2*)&sP[(t & 3) * 2048 + r16 * 128 + jb];
            float sx = (mv.x == 0) ? (eA - Pw.x) : 0.f;
            float sy = (mv.y == 0) ? (eB - Pw.y) : 0.f;
            sS2[(t & 3) * 1088 + r16 * 68 + spair] = packbf(sx, sy);
        }
    }

    // drain: AV-mma for supertiles 14, 15
    __syncthreads();
    #pragma unroll
    for (int u = 0; u < 2; u++) {
        int tp = NSUP - 2 + u;
        const unsigned* Sb = sS2 + (tp & 3) * 1088;
        const unsigned* Vb = (const unsigned*)(sm_raw + 32768 + (tp % 6) * 8704);
        unsigned a0 = Sb[g * 68 + ks * 8 + tig];
        unsigned a1 = Sb[(g + 8) * 68 + ks * 8 + tig];
        unsigned a2 = Sb[g * 68 + ks * 8 + tig + 4];
        unsigned a3 = Sb[(g + 8) * 68 + ks * 8 + tig + 4];
        unsigned b0 = Vb[(nc * 8 + g) * 68 + ks * 8 + tig];
        unsigned b1 = Vb[(nc * 8 + g) * 68 + ks * 8 + tig + 4];
        MMA_BF16(av0, av1, av2, av3, a0, a1, a2, a3, b0, b1);
    }
    __syncthreads();

    // write AV fragments to reduction buffer + stage epilogue consts
    {
        int jc = nc * 8 + 2 * tig;
        *(float2*)&sRed[(ks * 16 + g) * 32 + jc]     = make_float2(av0, av1);
        *(float2*)&sRed[(ks * 16 + g + 8) * 32 + jc] = make_float2(av2, av3);
    }
    for (int idx = tid; idx < RFEAT * DIM; idx += 1024) sM[idx] = g_M[idx];
    for (int idx = tid; idx < DIM * HDIM; idx += 1024) { sW1[idx] = W1[idx]; sW2[idx] = W2[idx]; }
    __syncthreads();

    if (h == 0) {
        float lr = 0.f;
        #pragma unroll
        for (int r = 0; r < RFEAT; r++) lr = fmaf(sPQ[r16 * RFEAT + r], sM[r * DIM + lane], lr);

        float attn = lr;
        #pragma unroll
        for (int kk = 0; kk < 8; kk++) attn += sRed[(kk * 16 + r16) * 32 + lane];

        float denom = fmaxf(warp_sum(attn), 1e-6f);
        float a = attn / denom;

        sZ1[r16 * DIM + lane] = a;     // temp staging for Wo matmul
        __syncwarp();
        float o = sVec[lane];   // bo
        #pragma unroll
        for (int c = 0; c < DIM; c++) o = fmaf(sZ1[r16 * DIM + c], sWo[c * DIM + lane], o);

        // LN1
        float x = Z[i * DIM + lane] + o;
        float mu = warp_sum(x) * (1.f / 32.f);
        float dd = x - mu;
        float var = warp_sum(dd * dd) * (1.f / 32.f);
        float z1 = dd * rsqrtf(var + 1e-5f) * sVec[64 + lane] + sVec[96 + lane];
        __syncwarp();
        sZ1[r16 * DIM + lane] = z1;
        __syncwarp();

        // FFN up + relu
        float hh[4];
        #pragma unroll
        for (int u = 0; u < 4; u++) hh[u] = sb1[lane + u * 32];
        #pragma unroll
        for (int k = 0; k < DIM; k++) {
            float zk = sZ1[r16 * DIM + k];
            #pragma unroll
            for (int u = 0; u < 4; u++) hh[u] = fmaf(zk, sW1[k * HDIM + lane + u * 32], hh[u]);
        }
        #pragma unroll
        for (int u = 0; u < 4; u++) sH[r16 * HDIM + lane + u * 32] = fmaxf(hh[u], 0.f);
        __syncwarp();

        // FFN down
        float o0 = sVec[32 + lane], o1 = 0.f, o2 = 0.f, o3 = 0.f;
        #pragma unroll
        for (int j = 0; j < HDIM; j += 4) {
            o0 = fmaf(sH[r16 * HDIM + j + 0], sW2[(j + 0) * DIM + lane], o0);
            o1 = fmaf(sH[r16 * HDIM + j + 1], sW2[(j + 1) * DIM + lane], o1);
            o2 = fmaf(sH[r16 * HDIM + j + 2], sW2[(j + 2) * DIM + lane], o2);
            o3 = fmaf(sH[r16 * HDIM + j + 3], sW2[(j + 3) * DIM + lane], o3);
        }
        float y = z1 + ((o0 + o1) + (o2 + o3));

        // LN2
        float mu2 = warp_sum(y) * (1.f / 32.f);
        float dd2 = y - mu2;
        float var2 = warp_sum(dd2 * dd2) * (1.f / 32.f);
        out[i * DIM + lane] = dd2 * rsqrtf(var2 + 1e-5f) * sVec[128 + lane] + sVec[160 + lane];
    }
}

// ---------------------------------------------------------------------
extern "C" void kernel_launch(void* const* d_in, const int* in_sizes, int n_in,
                              void* d_out, int out_size)
{
    const float* Z    = (const float*)d_in[0];
    const int*   mask = (const int*)  d_in[1];
    const float* Wq = (const float*)d_in[2],  *bq = (const float*)d_in[3];
    const float* Wk = (const float*)d_in[4],  *bk = (const float*)d_in[5];
    const float* Wv = (const float*)d_in[6],  *bv = (const float*)d_in[7];
    const float* Wo = (const float*)d_in[8],  *bo = (const float*)d_in[9];
    const float* W1 = (const float*)d_in[10], *b1 = (const float*)d_in[11];
    const float* W2 = (const float*)d_in[12], *b2 = (const float*)d_in[13];
    const float* g1 = (const float*)d_in[14], *be1 = (const float*)d_in[15];
    const float* g2 = (const float*)d_in[16], *be2 = (const float*)d_in[17];
    const float* omega = (const float*)d_in[18];

    cudaFuncSetAttribute(k3_attn, cudaFuncAttributeMaxDynamicSharedMemorySize, K3_SMEM_BYTES);

    void* mptr = nullptr;
    cudaGetSymbolAddress(&mptr, g_M);
    cudaMemsetAsync(mptr, 0, RFEAT * DIM * sizeof(float));

    k1_proj<<<N_TOK / 16, 512>>>(Z, Wq, bq, Wk, bk, Wv, bv, omega);
    k3_attn<<<N_TOK / 16, 1024, K3_SMEM_BYTES>>>(mask, Wo, bo, Z,
                                                 W1, b1, W2, b2,
                                                 g1, be1, g2, be2, (float*)d_out);
}